// round 1
// baseline (speedup 1.0000x reference)
#include <cuda_runtime.h>
#include <math.h>

// Problem constants: N=4, R=16384, K=96
#define NB   4
#define RB   16384
#define KS   96
#define KM   95                 // K-1 midpoint samples
#define RAYS (NB * RB)          // 65536 rays

// Global min/max of depth midpoints (bit patterns of positive floats)
__device__ unsigned g_min_bits;
__device__ unsigned g_max_bits;

__global__ void init_minmax_kernel() {
    g_min_bits = 0x7F800000u;   // +inf
    g_max_bits = 0x00000000u;   // 0.0f (depths are positive)
}

// Depths are sorted along K per ray, so the per-ray min midpoint is
// 0.5*(d[0]+d[1]) and max is 0.5*(d[K-2]+d[K-1]). One thread per ray,
// warp-reduce, then one atomic per warp (avoids single-address atomic storm).
__global__ void __launch_bounds__(256) minmax_kernel(const float* __restrict__ depths) {
    int ray = blockIdx.x * blockDim.x + threadIdx.x;
    float mn = __int_as_float(0x7F800000);
    float mx = 0.0f;
    if (ray < RAYS) {
        const float* d = depths + (size_t)ray * KS;
        mn = 0.5f * (d[0] + d[1]);
        mx = 0.5f * (d[KS - 2] + d[KS - 1]);
    }
    #pragma unroll
    for (int off = 16; off; off >>= 1) {
        mn = fminf(mn, __shfl_down_sync(0xffffffffu, mn, off));
        mx = fmaxf(mx, __shfl_down_sync(0xffffffffu, mx, off));
    }
    if ((threadIdx.x & 31) == 0) {
        atomicMin(&g_min_bits, __float_as_uint(mn));
        atomicMax(&g_max_bits, __float_as_uint(mx));
    }
}

// One warp per ray. 3 chunks of 32 lanes cover the 95 midpoints.
// Transmittance = exclusive multiplicative scan of (1 - alpha + 1e-10),
// done with a warp Hillis-Steele scan + cross-chunk carry.
__global__ void __launch_bounds__(256) render_kernel(
    const float* __restrict__ rgbs,     // [RAYS, K, 3]
    const float* __restrict__ sigmas,   // [RAYS, K]
    const float* __restrict__ depths,   // [RAYS, K]
    float* __restrict__ out_rgb,        // [RAYS, 3]
    float* __restrict__ out_depth,      // [RAYS]
    float* __restrict__ out_w)          // [RAYS, KM]
{
    int warp = (blockIdx.x * blockDim.x + threadIdx.x) >> 5;
    int lane = threadIdx.x & 31;
    if (warp >= RAYS) return;

    const float* d  = depths + (size_t)warp * KS;
    const float* s  = sigmas + (size_t)warp * KS;
    const float* rg = rgbs   + (size_t)warp * KS * 3;
    float* wout     = out_w  + (size_t)warp * KM;

    float carry = 1.0f;     // product of (1-alpha+eps) over all previous chunks
    float wsum = 0.0f, ar = 0.0f, ag = 0.0f, ab = 0.0f, ad = 0.0f;

    #pragma unroll
    for (int c = 0; c < 3; ++c) {
        int i = c * 32 + lane;
        bool valid = (i < KM);

        float d0 = 0.f, d1 = 0.f, s0 = 0.f, s1 = 0.f;
        float r0x = 0.f, r0y = 0.f, r0z = 0.f;
        float r1x = 0.f, r1y = 0.f, r1z = 0.f;
        if (valid) {
            d0 = d[i];  d1 = d[i + 1];
            s0 = s[i];  s1 = s[i + 1];
            r0x = rg[3 * i + 0]; r0y = rg[3 * i + 1]; r0z = rg[3 * i + 2];
            r1x = rg[3 * i + 3]; r1y = rg[3 * i + 4]; r1z = rg[3 * i + 5];
        }

        float delta = d1 - d0;
        float sm    = 0.5f * (s0 + s1) - 1.0f;
        // stable softplus: max(x,0) + log1p(exp(-|x|))
        float sp    = fmaxf(sm, 0.0f) + log1pf(expf(-fabsf(sm)));
        float alpha = valid ? (1.0f - expf(-delta * sp)) : 0.0f;
        float t     = valid ? (1.0f - alpha + 1e-10f) : 1.0f;

        // inclusive multiplicative warp scan (Hillis-Steele)
        float p = t;
        #pragma unroll
        for (int off = 1; off < 32; off <<= 1) {
            float v = __shfl_up_sync(0xffffffffu, p, off);
            if (lane >= off) p *= v;
        }
        float excl = __shfl_up_sync(0xffffffffu, p, 1);
        if (lane == 0) excl = 1.0f;
        float trans = carry * excl;
        carry *= __shfl_sync(0xffffffffu, p, 31);

        float w = alpha * trans;
        if (valid) {
            wout[i] = w;
            wsum += w;
            ar += w * 0.5f * (r0x + r1x);
            ag += w * 0.5f * (r0y + r1y);
            ab += w * 0.5f * (r0z + r1z);
            ad += w * 0.5f * (d0 + d1);
        }
    }

    // warp reduction of the 5 accumulators
    #pragma unroll
    for (int off = 16; off; off >>= 1) {
        wsum += __shfl_down_sync(0xffffffffu, wsum, off);
        ar   += __shfl_down_sync(0xffffffffu, ar,   off);
        ag   += __shfl_down_sync(0xffffffffu, ag,   off);
        ab   += __shfl_down_sync(0xffffffffu, ab,   off);
        ad   += __shfl_down_sync(0xffffffffu, ad,   off);
    }

    if (lane == 0) {
        out_rgb[warp * 3 + 0] = ar * 2.0f - 1.0f;
        out_rgb[warp * 3 + 1] = ag * 2.0f - 1.0f;
        out_rgb[warp * 3 + 2] = ab * 2.0f - 1.0f;

        float cd = ad / wsum;
        if (isnan(cd)) cd = __int_as_float(0x7F800000);   // nan_to_num(nan=inf)
        float gmin = __uint_as_float(g_min_bits);
        float gmax = __uint_as_float(g_max_bits);
        cd = fminf(fmaxf(cd, gmin), gmax);                // clip
        out_depth[warp] = cd;
    }
}

extern "C" void kernel_launch(void* const* d_in, const int* in_sizes, int n_in,
                              void* d_out, int out_size) {
    const float* rgbs   = (const float*)d_in[0];
    const float* sigmas = (const float*)d_in[1];
    const float* depths = (const float*)d_in[2];

    float* out = (float*)d_out;
    float* out_rgb   = out;                       // 65536*3 = 196608
    float* out_depth = out + (size_t)RAYS * 3;    // 65536
    float* out_w     = out + (size_t)RAYS * 4;    // 65536*95

    init_minmax_kernel<<<1, 1>>>();
    minmax_kernel<<<(RAYS + 255) / 256, 256>>>(depths);

    // one warp per ray: 8 warps per 256-thread block
    int blocks = (RAYS + 7) / 8;
    render_kernel<<<blocks, 256>>>(rgbs, sigmas, depths, out_rgb, out_depth, out_w);
}

// round 2
// speedup vs baseline: 1.2069x; 1.2069x over previous
#include <cuda_runtime.h>
#include <math.h>

// Problem constants: N=4, R=16384, K=96
#define KS   96
#define KM   95                 // K-1 midpoint samples
#define RAYS (4 * 16384)        // 65536 rays

#define FULL 0xffffffffu

// One warp per ray. 3 chunks of 32 lanes cover the 95 midpoints.
// Each lane loads only its own 3 samples per array (15 LDG total, batched
// up-front); the i+1 neighbor comes via warp shuffle. Transmittance is an
// exclusive multiplicative Hillis-Steele warp scan with cross-chunk carry.
//
// The reference's global depth clip is a provable no-op: composite_depth is a
// convex combination of the ray's own midpoints (weights >= 0), which lie
// inside [global_min_mid, global_max_mid]. wsum > 0 always (softplus > 0,
// sorted deltas > 0), so the NaN path is dead too. Hence: single kernel.
__global__ void __launch_bounds__(256) render_kernel(
    const float* __restrict__ rgbs,     // [RAYS, K, 3]
    const float* __restrict__ sigmas,   // [RAYS, K]
    const float* __restrict__ depths,   // [RAYS, K]
    float* __restrict__ out_rgb,        // [RAYS, 3]
    float* __restrict__ out_depth,      // [RAYS]
    float* __restrict__ out_w)          // [RAYS, KM]
{
    int warp = (blockIdx.x * blockDim.x + threadIdx.x) >> 5;
    int lane = threadIdx.x & 31;
    if (warp >= RAYS) return;

    const float* d  = depths + (size_t)warp * KS;
    const float* s  = sigmas + (size_t)warp * KS;
    const float* rg = rgbs   + (size_t)warp * KS * 3;
    float* wout     = out_w  + (size_t)warp * KM;

    // Front-batched loads: 15 independent LDGs for max MLP.
    float dv[3], sv[3], rx[3], ry[3], rz[3];
    #pragma unroll
    for (int c = 0; c < 3; ++c) {
        int i = c * 32 + lane;
        dv[c] = d[i];
        sv[c] = s[i];
        rx[c] = rg[3 * i + 0];
        ry[c] = rg[3 * i + 1];
        rz[c] = rg[3 * i + 2];
    }

    float carry = 1.0f;     // product of (1-alpha+eps) over previous chunks
    float wsum = 0.0f, ar = 0.0f, ag = 0.0f, ab = 0.0f, ad = 0.0f;

    #pragma unroll
    for (int c = 0; c < 3; ++c) {
        bool valid = (c < 2) | (lane < 31);   // only chunk 2, lane 31 invalid
        int cn = (c + 1 < 3) ? c + 1 : 0;     // garbage for c==2 (masked)

        // neighbor (i+1) values: shfl_down within chunk, lane31 takes lane0
        // of the next chunk.
        float d1 = __shfl_down_sync(FULL, dv[c], 1);
        float s1 = __shfl_down_sync(FULL, sv[c], 1);
        float x1 = __shfl_down_sync(FULL, rx[c], 1);
        float y1 = __shfl_down_sync(FULL, ry[c], 1);
        float z1 = __shfl_down_sync(FULL, rz[c], 1);
        float dB = __shfl_sync(FULL, dv[cn], 0);
        float sB = __shfl_sync(FULL, sv[cn], 0);
        float xB = __shfl_sync(FULL, rx[cn], 0);
        float yB = __shfl_sync(FULL, ry[cn], 0);
        float zB = __shfl_sync(FULL, rz[cn], 0);
        if (lane == 31) { d1 = dB; s1 = sB; x1 = xB; y1 = yB; z1 = zB; }

        float delta = d1 - dv[c];
        float sm    = 0.5f * (sv[c] + s1) - 1.0f;
        // stable softplus: max(x,0) + log1p(exp(-|x|))
        float sp    = fmaxf(sm, 0.0f) + log1pf(expf(-fabsf(sm)));
        float alpha = 1.0f - expf(-delta * sp);
        float t     = valid ? (1.0f - alpha + 1e-10f) : 1.0f;

        // inclusive multiplicative warp scan (Hillis-Steele)
        float p = t;
        #pragma unroll
        for (int off = 1; off < 32; off <<= 1) {
            float v = __shfl_up_sync(FULL, p, off);
            if (lane >= off) p *= v;
        }
        float excl = __shfl_up_sync(FULL, p, 1);
        if (lane == 0) excl = 1.0f;
        float trans = carry * excl;
        carry *= __shfl_sync(FULL, p, 31);

        float w = alpha * trans;
        if (valid) {
            wout[c * 32 + lane] = w;
            wsum += w;
            ar = fmaf(w, 0.5f * (rx[c] + x1), ar);
            ag = fmaf(w, 0.5f * (ry[c] + y1), ag);
            ab = fmaf(w, 0.5f * (rz[c] + z1), ab);
            ad = fmaf(w, 0.5f * (dv[c] + d1), ad);
        }
    }

    // warp reduction of the 5 accumulators
    #pragma unroll
    for (int off = 16; off; off >>= 1) {
        wsum += __shfl_down_sync(FULL, wsum, off);
        ar   += __shfl_down_sync(FULL, ar,   off);
        ag   += __shfl_down_sync(FULL, ag,   off);
        ab   += __shfl_down_sync(FULL, ab,   off);
        ad   += __shfl_down_sync(FULL, ad,   off);
    }

    if (lane == 0) {
        out_rgb[warp * 3 + 0] = ar * 2.0f - 1.0f;
        out_rgb[warp * 3 + 1] = ag * 2.0f - 1.0f;
        out_rgb[warp * 3 + 2] = ab * 2.0f - 1.0f;
        out_depth[warp] = ad / wsum;   // clip is a provable no-op (see above)
    }
}

extern "C" void kernel_launch(void* const* d_in, const int* in_sizes, int n_in,
                              void* d_out, int out_size) {
    const float* rgbs   = (const float*)d_in[0];
    const float* sigmas = (const float*)d_in[1];
    const float* depths = (const float*)d_in[2];

    float* out = (float*)d_out;
    float* out_rgb   = out;                       // 65536*3 = 196608
    float* out_depth = out + (size_t)RAYS * 3;    // 65536
    float* out_w     = out + (size_t)RAYS * 4;    // 65536*95

    // one warp per ray: 8 warps per 256-thread block
    int blocks = (RAYS + 7) / 8;
    render_kernel<<<blocks, 256>>>(rgbs, sigmas, depths, out_rgb, out_depth, out_w);
}

// round 4
// speedup vs baseline: 1.2783x; 1.0591x over previous
#include <cuda_runtime.h>
#include <math.h>

// Problem constants: N=4, R=16384, K=96
#define KS   96
#define KM   95                 // K-1 midpoint samples
#define RAYS (4 * 16384)        // 65536 rays

#define FULL  0xffffffffu
#define LOG2E 1.4426950408889634f

__device__ __forceinline__ float ex2f(float x) {
    float r;
    asm("ex2.approx.ftz.f32 %0, %1;" : "=f"(r) : "f"(x));
    return r;
}
__device__ __forceinline__ float lg2f(float x) {
    float r;
    asm("lg2.approx.ftz.f32 %0, %1;" : "=f"(r) : "f"(x));
    return r;
}

// One warp per ray; 3 chunks of 32 lanes cover samples i = 0..95.
// Key identity: sum_i w_i * 0.5*(x_i + x_{i+1}) = 0.5 * sum_j x_j*(w_j + w_{j-1})
// (w_{-1} = w_95 = 0), so rgb/depth midpoints need NO neighbor shuffles —
// only d and s (for alpha) do, plus one shfl_up of w after the scan.
// composite_rgb final = (0.5*S)*2 - 1 = S - 1.
// Global depth clip + NaN path are provable no-ops (convex combination of the
// ray's own midpoints; wsum > 0 since softplus > 0 and sorted deltas > 0).
__global__ void __launch_bounds__(256) render_kernel(
    const float* __restrict__ rgbs,     // [RAYS, K, 3]
    const float* __restrict__ sigmas,   // [RAYS, K]
    const float* __restrict__ depths,   // [RAYS, K]
    float* __restrict__ out_rgb,        // [RAYS, 3]
    float* __restrict__ out_depth,      // [RAYS]
    float* __restrict__ out_w)          // [RAYS, KM]
{
    int warp = (blockIdx.x * blockDim.x + threadIdx.x) >> 5;
    int lane = threadIdx.x & 31;
    if (warp >= RAYS) return;

    const float* d  = depths + (size_t)warp * KS;
    const float* s  = sigmas + (size_t)warp * KS;
    const float* rg = rgbs   + (size_t)warp * KS * 3;
    float* wout     = out_w  + (size_t)warp * KM;

    // Front-batched loads: 15 independent LDGs for max MLP.
    float dv[3], sv[3], rx[3], ry[3], rz[3];
    #pragma unroll
    for (int c = 0; c < 3; ++c) {
        int i = c * 32 + lane;
        dv[c] = d[i];
        sv[c] = s[i];
        rx[c] = rg[3 * i + 0];
        ry[c] = rg[3 * i + 1];
        rz[c] = rg[3 * i + 2];
    }

    float carry  = 1.0f;   // running product of (1-alpha+eps) over prev chunks
    float wcarry = 0.0f;   // w of lane 31 of previous chunk (w_{j-1} chain)
    float wsum = 0.0f, ar = 0.0f, ag = 0.0f, ab = 0.0f, ad = 0.0f;

    #pragma unroll
    for (int c = 0; c < 3; ++c) {
        bool valid = (c < 2) | (lane < 31);   // only i==95 invalid
        int cn = (c + 1 < 3) ? c + 1 : 0;     // masked garbage for c==2

        // neighbor (i+1) for d and s only
        float d1 = __shfl_down_sync(FULL, dv[c], 1);
        float s1 = __shfl_down_sync(FULL, sv[c], 1);
        float dB = __shfl_sync(FULL, dv[cn], 0);
        float sB = __shfl_sync(FULL, sv[cn], 0);
        if (lane == 31) { d1 = dB; s1 = sB; }

        float delta = d1 - dv[c];
        float sm    = 0.5f * (sv[c] + s1) - 1.0f;
        // softplus(sm) * log2e, stable fast form via MUFU ex2/lg2:
        float em    = ex2f(-fabsf(sm) * LOG2E);
        float L     = fmaxf(sm, 0.0f) * LOG2E + lg2f(1.0f + em);
        float alpha = 1.0f - ex2f(-delta * L);
        float t     = valid ? (1.0f - alpha + 1e-10f) : 1.0f;

        // inclusive multiplicative warp scan (Hillis-Steele)
        float p = t;
        #pragma unroll
        for (int off = 1; off < 32; off <<= 1) {
            float v = __shfl_up_sync(FULL, p, off);
            if (lane >= off) p *= v;
        }
        float excl = __shfl_up_sync(FULL, p, 1);
        if (lane == 0) excl = 1.0f;
        float trans = carry * excl;
        carry *= __shfl_sync(FULL, p, 31);

        float w = valid ? alpha * trans : 0.0f;
        if (valid) wout[c * 32 + lane] = w;

        float wp = __shfl_up_sync(FULL, w, 1);       // w_{j-1}
        if (lane == 0) wp = wcarry;
        wcarry = __shfl_sync(FULL, w, 31);

        float ww = w + wp;
        wsum += w;
        ar = fmaf(ww, rx[c], ar);
        ag = fmaf(ww, ry[c], ag);
        ab = fmaf(ww, rz[c], ab);
        ad = fmaf(ww, dv[c], ad);
    }

    // warp reduction of the 5 accumulators
    #pragma unroll
    for (int off = 16; off; off >>= 1) {
        wsum += __shfl_down_sync(FULL, wsum, off);
        ar   += __shfl_down_sync(FULL, ar,   off);
        ag   += __shfl_down_sync(FULL, ag,   off);
        ab   += __shfl_down_sync(FULL, ab,   off);
        ad   += __shfl_down_sync(FULL, ad,   off);
    }

    if (lane == 0) {
        out_rgb[warp * 3 + 0] = ar - 1.0f;       // (0.5*ar)*2 - 1
        out_rgb[warp * 3 + 1] = ag - 1.0f;
        out_rgb[warp * 3 + 2] = ab - 1.0f;
        out_depth[warp] = (0.5f * ad) / wsum;    // clip/NaN path: no-op
    }
}

extern "C" void kernel_launch(void* const* d_in, const int* in_sizes, int n_in,
                              void* d_out, int out_size) {
    const float* rgbs   = (const float*)d_in[0];
    const float* sigmas = (const float*)d_in[1];
    const float* depths = (const float*)d_in[2];

    float* out = (float*)d_out;
    float* out_rgb   = out;                       // 65536*3
    float* out_depth = out + (size_t)RAYS * 3;    // 65536
    float* out_w     = out + (size_t)RAYS * 4;    // 65536*95

    int blocks = (RAYS + 7) / 8;                  // one warp per ray
    render_kernel<<<blocks, 256>>>(rgbs, sigmas, depths, out_rgb, out_depth, out_w);
}